// round 7
// baseline (speedup 1.0000x reference)
#include <cuda_runtime.h>
#include <cstdint>

// ---------------- problem constants ----------------
#define TB 16
#define TN 1024
#define TD 768
#define TH 12
#define TP 16
#define THD 64
#define TFF 3072
#define TNK (TP + TN)      // 1040
#define TBH (TB * TH)      // 192
#define TM (TB * TN)       // 16384

// ---------------- scratch ----------------
__device__ float g_h[(size_t)TM * TD];
__device__ float g_qkv[(size_t)TM * 3 * TD];
__device__ float g_kb[(size_t)TBH * TNK * THD];
__device__ float g_vb[(size_t)TBH * TNK * THD];
__device__ float g_ao[(size_t)TM * TD];
__device__ float g_x1[(size_t)TM * TD];
__device__ float g_mm[(size_t)TM * TFF];

// ---------------- helpers ----------------
__device__ __forceinline__ uint32_t f2tf(float f) {
    uint32_t u;
    asm("cvt.rna.tf32.f32 %0, %1;" : "=r"(u) : "f"(f));
    return u;
}
__device__ __forceinline__ float f2tff(float f) {
    return __uint_as_float(f2tf(f));
}

__device__ __forceinline__ void mma8(float c[4], const uint32_t a[4], const uint32_t b[2]) {
    asm volatile(
        "mma.sync.aligned.m16n8k8.row.col.f32.tf32.tf32.f32 "
        "{%0,%1,%2,%3},{%4,%5,%6,%7},{%8,%9},{%0,%1,%2,%3};\n"
        : "+f"(c[0]), "+f"(c[1]), "+f"(c[2]), "+f"(c[3])
        : "r"(a[0]), "r"(a[1]), "r"(a[2]), "r"(a[3]), "r"(b[0]), "r"(b[1]));
}

// ---------------- tiled TF32 GEMM, fragment-permuted SMEM ----------------
// C = A (MxK) @ B^T (B is [N,K]).  Block tile 128x192, K-tile 16, 256 threads,
// 8 warps in 2(m) x 4(n), warp tile 64x48.
// SMEM layouts (per k-step block, tf32 values stored at staging):
//   A: [kstep][ mf*128 + g*16 + tg*4 + e ]   e = khi*2 + rowpair  -> frag = LDS.128
//   B: [kstep][ nf8*64 + g*8 + tg*2 + e ]    e = khi              -> frag = LDS.64
template <bool BIAS, bool RES, bool GELU>
__global__ void __launch_bounds__(256)
gemm_kernel(const float* __restrict__ A, const float* __restrict__ B,
            const float* __restrict__ bias, const float* __restrict__ res,
            float* __restrict__ C, int M, int N, int K) {
    __shared__ float sA[2][2048];   // 128 x 16
    __shared__ float sB[2][3072];   // 192 x 16

    const int m0 = blockIdx.y * 128;
    const int n0 = blockIdx.x * 192;
    const int t = threadIdx.x;
    const int warp = t >> 5, lane = t & 31;
    const int wmi = warp >> 2, wni = warp & 3;   // warp tile (wmi*64, wni*48)
    const int g = lane >> 2, tg = lane & 3;

    float acc[4][6][4];
#pragma unroll
    for (int i = 0; i < 4; i++)
#pragma unroll
        for (int j = 0; j < 6; j++)
#pragma unroll
            for (int r = 0; r < 4; r++) acc[i][j][r] = 0.f;

    const int nk = K >> 4;

    // loader mapping: each thread owns 4 consecutive k of some rows
    const int arow = t >> 2;            // 0..63
    const int ac = (t & 3) * 4;         // 0,4,8,12
    const int kstepL = ac >> 3;         // 0/1
    const int khiL = (ac >> 2) & 1;     // 0/1

    // precomputed staging bases
    int abase[2], bbase[3];
#pragma unroll
    for (int u = 0; u < 2; u++) {
        int r = arow + u * 64;
        int mf = r >> 4, gg = r & 7, pr = (r >> 3) & 1;
        abase[u] = kstepL * 1024 + mf * 128 + gg * 16 + (khiL * 2 + pr);
    }
#pragma unroll
    for (int u = 0; u < 3; u++) {
        int r = arow + u * 64;
        int nf8 = r >> 3, gg = r & 7;
        bbase[u] = kstepL * 1536 + nf8 * 64 + gg * 8 + khiL;
    }

    float4 ra[2], rb[3];
    auto gload = [&](int kt) {
        const int k0 = (kt << 4) + ac;
#pragma unroll
        for (int u = 0; u < 2; u++)
            ra[u] = *(const float4*)(A + (long long)(m0 + arow + u * 64) * K + k0);
#pragma unroll
        for (int u = 0; u < 3; u++)
            rb[u] = *(const float4*)(B + (long long)(n0 + arow + u * 64) * K + k0);
    };

    auto sstore = [&](int buf) {
#pragma unroll
        for (int u = 0; u < 2; u++) {
            float* p = &sA[buf][abase[u]];
            p[0]  = f2tff(ra[u].x);
            p[4]  = f2tff(ra[u].y);
            p[8]  = f2tff(ra[u].z);
            p[12] = f2tff(ra[u].w);
        }
#pragma unroll
        for (int u = 0; u < 3; u++) {
            float* p = &sB[buf][bbase[u]];
            p[0] = f2tff(rb[u].x);
            p[2] = f2tff(rb[u].y);
            p[4] = f2tff(rb[u].z);
            p[6] = f2tff(rb[u].w);
        }
    };

    gload(0);
    sstore(0);
    __syncthreads();

    int buf = 0;
    for (int kt = 0; kt < nk; kt++) {
        if (kt + 1 < nk) gload(kt + 1);
#pragma unroll
        for (int ks = 0; ks < 2; ks++) {
            uint32_t af[4][4], bf[6][2];
#pragma unroll
            for (int i = 0; i < 4; i++) {
                float4 v = *(const float4*)
                    (&sA[buf][ks * 1024 + (wmi * 4 + i) * 128 + g * 16 + tg * 4]);
                af[i][0] = __float_as_uint(v.x);
                af[i][1] = __float_as_uint(v.y);
                af[i][2] = __float_as_uint(v.z);
                af[i][3] = __float_as_uint(v.w);
            }
#pragma unroll
            for (int j = 0; j < 6; j++) {
                float2 v = *(const float2*)
                    (&sB[buf][ks * 1536 + (wni * 6 + j) * 64 + g * 8 + tg * 2]);
                bf[j][0] = __float_as_uint(v.x);
                bf[j][1] = __float_as_uint(v.y);
            }
#pragma unroll
            for (int i = 0; i < 4; i++)
#pragma unroll
                for (int j = 0; j < 6; j++) mma8(acc[i][j], af[i], bf[j]);
        }
        if (kt + 1 < nk) sstore(buf ^ 1);
        __syncthreads();
        buf ^= 1;
    }

    // epilogue (float2 stores)
#pragma unroll
    for (int i = 0; i < 4; i++) {
#pragma unroll
        for (int j = 0; j < 6; j++) {
            int m = m0 + wmi * 64 + i * 16 + g;
            int n = n0 + wni * 48 + j * 8 + tg * 2;
#pragma unroll
            for (int rr = 0; rr < 2; rr++) {
                int mm = m + rr * 8;
                float v0 = acc[i][j][rr * 2 + 0];
                float v1 = acc[i][j][rr * 2 + 1];
                if (BIAS) { v0 += bias[n]; v1 += bias[n + 1]; }
                if (GELU) {
                    v0 = v0 / (1.f + __expf(-1.702f * v0));
                    v1 = v1 / (1.f + __expf(-1.702f * v1));
                }
                if (RES) {
                    float2 rv = *(const float2*)(res + (long long)mm * N + n);
                    v0 += rv.x; v1 += rv.y;
                }
                float2 o; o.x = v0; o.y = v1;
                *(float2*)(C + (long long)mm * N + n) = o;
            }
        }
    }
}

// ---------------- LayerNorm ----------------
__global__ void ln_kernel(const float* __restrict__ x, const float* __restrict__ gw,
                          const float* __restrict__ bw, float* __restrict__ out) {
    long long row = blockIdx.x;
    const float* xr = x + row * TD;
    float* orow = out + row * TD;
    int t = threadIdx.x;
    float v[3];
    float s = 0.f, s2 = 0.f;
#pragma unroll
    for (int i = 0; i < 3; i++) {
        v[i] = xr[t + i * 256];
        s += v[i];
        s2 += v[i] * v[i];
    }
#pragma unroll
    for (int o = 16; o > 0; o >>= 1) {
        s += __shfl_xor_sync(0xffffffffu, s, o);
        s2 += __shfl_xor_sync(0xffffffffu, s2, o);
    }
    __shared__ float r1[8], r2[8];
    if ((t & 31) == 0) { r1[t >> 5] = s; r2[t >> 5] = s2; }
    __syncthreads();
    s = 0.f; s2 = 0.f;
#pragma unroll
    for (int w = 0; w < 8; w++) { s += r1[w]; s2 += r2[w]; }
    float mu = s * (1.f / TD);
    float var = s2 * (1.f / TD) - mu * mu;
    float inv = rsqrtf(var + 1e-5f);
#pragma unroll
    for (int i = 0; i < 3; i++) {
        int c = t + i * 256;
        orow[c] = (v[i] - mu) * inv * gw[c] + bw[c];
    }
}

// ---------------- K/V gather, merged + vectorized ----------------
__global__ void gather_kv_kernel(const float* __restrict__ qkv, const float* __restrict__ prompt,
                                 float* __restrict__ Kd, float* __restrict__ Vd) {
    int i = blockIdx.x * 256 + threadIdx.x;          // float4 index
    const int TOT = TBH * TNK * (THD / 4);
    if (i >= TOT) return;
    int d4 = i & 15;
    int tmp = i >> 4;
    int j = tmp % TNK;
    int zz = tmp / TNK;
    int b = zz / TH, h = zz % TH;
    float4 kv, vv;
    if (j < TP) {
        kv = *(const float4*)(prompt + (((long long)(b * 2 + 0) * TP + j) * TH + h) * THD + d4 * 4);
        vv = *(const float4*)(prompt + (((long long)(b * 2 + 1) * TP + j) * TH + h) * THD + d4 * 4);
    } else {
        long long base = (long long)(b * TN + (j - TP)) * (3 * TD) + h * THD + d4 * 4;
        kv = *(const float4*)(qkv + base + TD);
        vv = *(const float4*)(qkv + base + 2 * TD);
    }
    ((float4*)Kd)[i] = kv;
    ((float4*)Vd)[i] = vv;
}

// ---------------- fused flash attention ----------------
// K/V/P stored in SMEM already tf32-converted -> mainloop fragment loads are
// plain LDS with no cvt.
#define FA_SMEM_BYTES ((2 * 64 * 68 + 128 * 68) * 4)

__global__ void __launch_bounds__(256)
flash_kernel(const float* __restrict__ qkv, const float* __restrict__ Kb,
             const float* __restrict__ Vb, float* __restrict__ O) {
    extern __shared__ float sm[];
    float* sK = sm;
    float* sV = sm + 64 * 68;
    float* sP = sm + 2 * 64 * 68;

    const int z = blockIdx.y;
    const int b = z / TH, h = z % TH;
    const int q0 = blockIdx.x * 128;
    const int t = threadIdx.x, warp = t >> 5, lane = t & 31;
    const int g = lane >> 2, tg = lane & 3;
    const int wm = warp * 16;

#pragma unroll
    for (int u = 0; u < 8; u++) {
        int idx = t + u * 256;
        int r = idx >> 4, c4 = (idx & 15) * 4;
        float4 v = *(const float4*)(qkv + (long long)(b * TN + q0 + r) * (3 * TD) + h * THD + c4);
        float* p = &sP[r * 68 + c4];
        p[0] = v.x; p[1] = v.y; p[2] = v.z; p[3] = v.w;
    }
    __syncthreads();
    uint32_t qf[8][4];
#pragma unroll
    for (int ks = 0; ks < 8; ks++) {
        const float* pa = &sP[(wm + g) * 68 + ks * 8 + tg];
        qf[ks][0] = f2tf(pa[0]);
        qf[ks][1] = f2tf(pa[8 * 68]);
        qf[ks][2] = f2tf(pa[4]);
        qf[ks][3] = f2tf(pa[8 * 68 + 4]);
    }
    __syncthreads();

    float acc[8][4];
#pragma unroll
    for (int j = 0; j < 8; j++)
#pragma unroll
        for (int r = 0; r < 4; r++) acc[j][r] = 0.f;
    float m0 = -1e30f, m1 = -1e30f, l0 = 0.f, l1 = 0.f;

    const float* Kz = Kb + (long long)z * TNK * THD;
    const float* Vz = Vb + (long long)z * TNK * THD;

    for (int t0 = 0; t0 < TNK; t0 += 64) {
        // load K/V tile, tf32-convert at store
#pragma unroll
        for (int u = 0; u < 4; u++) {
            int idx = t + u * 256;
            int r = idx >> 4, c4 = (idx & 15) * 4;
            int key = t0 + r;
            float4 kk, vv;
            if (key < TNK) {
                kk = *(const float4*)(Kz + (long long)key * THD + c4);
                vv = *(const float4*)(Vz + (long long)key * THD + c4);
            } else {
                kk = make_float4(0.f, 0.f, 0.f, 0.f);
                vv = kk;
            }
            float* pk = &sK[r * 68 + c4];
            pk[0] = f2tff(kk.x); pk[1] = f2tff(kk.y);
            pk[2] = f2tff(kk.z); pk[3] = f2tff(kk.w);
            float* pv = &sV[r * 68 + c4];
            pv[0] = f2tff(vv.x); pv[1] = f2tff(vv.y);
            pv[2] = f2tff(vv.z); pv[3] = f2tff(vv.w);
        }
        __syncthreads();

        // S = Q @ K^T
        float s[8][4];
#pragma unroll
        for (int j = 0; j < 8; j++) {
            s[j][0] = s[j][1] = s[j][2] = s[j][3] = 0.f;
#pragma unroll
            for (int ks = 0; ks < 8; ks++) {
                uint32_t bf[2];
                const float* pb = &sK[(j * 8 + g) * 68 + ks * 8 + tg];
                bf[0] = __float_as_uint(pb[0]);
                bf[1] = __float_as_uint(pb[4]);
                mma8(s[j], qf[ks], bf);
            }
        }

        // online softmax
        float mx0 = -1e30f, mx1 = -1e30f;
#pragma unroll
        for (int j = 0; j < 8; j++) {
            int k0 = t0 + j * 8 + 2 * tg;
            if (k0 >= TNK) { s[j][0] = -1e30f; s[j][2] = -1e30f; }
            else           { s[j][0] *= 0.125f; s[j][2] *= 0.125f; }
            if (k0 + 1 >= TNK) { s[j][1] = -1e30f; s[j][3] = -1e30f; }
            else               { s[j][1] *= 0.125f; s[j][3] *= 0.125f; }
            mx0 = fmaxf(mx0, fmaxf(s[j][0], s[j][1]));
            mx1 = fmaxf(mx1, fmaxf(s[j][2], s[j][3]));
        }
        mx0 = fmaxf(mx0, __shfl_xor_sync(0xffffffffu, mx0, 1));
        mx0 = fmaxf(mx0, __shfl_xor_sync(0xffffffffu, mx0, 2));
        mx1 = fmaxf(mx1, __shfl_xor_sync(0xffffffffu, mx1, 1));
        mx1 = fmaxf(mx1, __shfl_xor_sync(0xffffffffu, mx1, 2));
        float mn0 = fmaxf(m0, mx0), mn1 = fmaxf(m1, mx1);
        float a0 = __expf(m0 - mn0), a1 = __expf(m1 - mn1);
        m0 = mn0; m1 = mn1;
        float sum0 = 0.f, sum1 = 0.f;
#pragma unroll
        for (int j = 0; j < 8; j++) {
            s[j][0] = __expf(s[j][0] - mn0);
            s[j][1] = __expf(s[j][1] - mn0);
            s[j][2] = __expf(s[j][2] - mn1);
            s[j][3] = __expf(s[j][3] - mn1);
            sum0 += s[j][0] + s[j][1];
            sum1 += s[j][2] + s[j][3];
            float* pp = &sP[(wm + g) * 68 + j * 8 + 2 * tg];
            pp[0] = f2tff(s[j][0]); pp[1] = f2tff(s[j][1]);
            pp[8 * 68] = f2tff(s[j][2]); pp[8 * 68 + 1] = f2tff(s[j][3]);
        }
        sum0 += __shfl_xor_sync(0xffffffffu, sum0, 1);
        sum0 += __shfl_xor_sync(0xffffffffu, sum0, 2);
        sum1 += __shfl_xor_sync(0xffffffffu, sum1, 1);
        sum1 += __shfl_xor_sync(0xffffffffu, sum1, 2);
        l0 = l0 * a0 + sum0;
        l1 = l1 * a1 + sum1;
#pragma unroll
        for (int j = 0; j < 8; j++) {
            acc[j][0] *= a0; acc[j][1] *= a0;
            acc[j][2] *= a1; acc[j][3] *= a1;
        }
        __syncwarp();

        // O += P @ V   (all operands pre-converted in SMEM)
#pragma unroll
        for (int ks = 0; ks < 8; ks++) {
            uint32_t af[4];
            const float* pa = &sP[(wm + g) * 68 + ks * 8 + tg];
            af[0] = __float_as_uint(pa[0]);
            af[1] = __float_as_uint(pa[8 * 68]);
            af[2] = __float_as_uint(pa[4]);
            af[3] = __float_as_uint(pa[8 * 68 + 4]);
#pragma unroll
            for (int j = 0; j < 8; j++) {
                uint32_t bf[2];
                bf[0] = __float_as_uint(sV[(ks * 8 + tg) * 68 + j * 8 + g]);
                bf[1] = __float_as_uint(sV[(ks * 8 + tg + 4) * 68 + j * 8 + g]);
                mma8(acc[j], af, bf);
            }
        }
        __syncthreads();
    }

    float i0 = 1.f / l0, i1 = 1.f / l1;
    int q = q0 + wm + g;
#pragma unroll
    for (int j = 0; j < 8; j++) {
        long long base = ((long long)(b * TN + q)) * TD + h * THD + j * 8 + 2 * tg;
        O[base] = acc[j][0] * i0;
        O[base + 1] = acc[j][1] * i0;
        O[base + (long long)8 * TD] = acc[j][2] * i1;
        O[base + (long long)8 * TD + 1] = acc[j][3] * i1;
    }
}

// ---------------- launch ----------------
extern "C" void kernel_launch(void* const* d_in, const int* in_sizes, int n_in,
                              void* d_out, int out_size) {
    const float* x      = (const float*)d_in[0];
    const float* prompt = (const float*)d_in[1];
    const float* qkv_w  = (const float*)d_in[2];
    const float* qkv_b  = (const float*)d_in[3];
    const float* out_w  = (const float*)d_in[4];
    const float* out_b  = (const float*)d_in[5];
    const float* ln1_g  = (const float*)d_in[6];
    const float* ln1_b  = (const float*)d_in[7];
    const float* ln2_g  = (const float*)d_in[8];
    const float* ln2_b  = (const float*)d_in[9];
    const float* fc1_w  = (const float*)d_in[10];
    const float* fc1_b  = (const float*)d_in[11];
    const float* fc2_w  = (const float*)d_in[12];
    const float* fc2_b  = (const float*)d_in[13];
    float* out = (float*)d_out;

    float *ph, *pqkv, *pkb, *pvb, *pao, *px1, *pm;
    cudaGetSymbolAddress((void**)&ph, g_h);
    cudaGetSymbolAddress((void**)&pqkv, g_qkv);
    cudaGetSymbolAddress((void**)&pkb, g_kb);
    cudaGetSymbolAddress((void**)&pvb, g_vb);
    cudaGetSymbolAddress((void**)&pao, g_ao);
    cudaGetSymbolAddress((void**)&px1, g_x1);
    cudaGetSymbolAddress((void**)&pm, g_mm);

    cudaFuncSetAttribute(flash_kernel, cudaFuncAttributeMaxDynamicSharedMemorySize,
                         FA_SMEM_BYTES);

    // 1. LN1
    ln_kernel<<<TM, 256>>>(x, ln1_g, ln1_b, ph);

    // 2. qkv = h @ qkv_w^T + qkv_b   [16384, 2304]
    gemm_kernel<true, false, false>
        <<<dim3(3 * TD / 192, TM / 128), 256>>>(ph, qkv_w, qkv_b, nullptr, pqkv,
                                                TM, 3 * TD, TD);

    // 3. gather K/V (prompt concat), merged
    gather_kv_kernel<<<(TBH * TNK * (THD / 4) + 255) / 256, 256>>>(pqkv, prompt, pkb, pvb);

    // 4. fused flash attention -> [B,N,D]
    flash_kernel<<<dim3(TN / 128, TBH), 256, FA_SMEM_BYTES>>>(pqkv, pkb, pvb, pao);

    // 5. x1 = x + O @ out_w^T + out_b
    gemm_kernel<true, true, false>
        <<<dim3(TD / 192, TM / 128), 256>>>(pao, out_w, out_b, x, px1, TM, TD, TD);

    // 6. LN2
    ln_kernel<<<TM, 256>>>(px1, ln2_g, ln2_b, ph);

    // 7. m = QuickGELU(h @ fc1_w^T + fc1_b)
    gemm_kernel<true, false, true>
        <<<dim3(TFF / 192, TM / 128), 256>>>(ph, fc1_w, fc1_b, nullptr, pm, TM, TFF, TD);

    // 8. out = x1 + m @ fc2_w^T + fc2_b
    gemm_kernel<true, true, false>
        <<<dim3(TD / 192, TM / 128), 256>>>(pm, fc2_w, fc2_b, px1, out, TM, TD, TFF);
}

// round 11
// speedup vs baseline: 1.2321x; 1.2321x over previous
#include <cuda_runtime.h>
#include <cstdint>

// ---------------- problem constants ----------------
#define TB 16
#define TN 1024
#define TD 768
#define TH 12
#define TP 16
#define THD 64
#define TFF 3072
#define TNK (TP + TN)      // 1040
#define TBH (TB * TH)      // 192
#define TM (TB * TN)       // 16384

// ---------------- scratch ----------------
__device__ float g_h[(size_t)TM * TD];
__device__ float g_qkv[(size_t)TM * 3 * TD];
__device__ float g_kb[(size_t)TBH * TNK * THD];
__device__ float g_vb[(size_t)TBH * TNK * THD];
__device__ float g_ao[(size_t)TM * TD];
__device__ float g_x1[(size_t)TM * TD];
__device__ float g_mm[(size_t)TM * TFF];

// ---------------- helpers ----------------
__device__ __forceinline__ uint32_t f2tf(float f) {
    uint32_t u;
    asm("cvt.rna.tf32.f32 %0, %1;" : "=r"(u) : "f"(f));
    return u;
}
__device__ __forceinline__ float f2tff(float f) {
    return __uint_as_float(f2tf(f));
}

__device__ __forceinline__ void mma8(float c[4], const uint32_t a[4], const uint32_t b[2]) {
    asm volatile(
        "mma.sync.aligned.m16n8k8.row.col.f32.tf32.tf32.f32 "
        "{%0,%1,%2,%3},{%4,%5,%6,%7},{%8,%9},{%0,%1,%2,%3};\n"
        : "+f"(c[0]), "+f"(c[1]), "+f"(c[2]), "+f"(c[3])
        : "r"(a[0]), "r"(a[1]), "r"(a[2]), "r"(a[3]), "r"(b[0]), "r"(b[1]));
}

// ---------------- tiled TF32 GEMM (R2 version: contiguous staging stores,
// tf32 pre-converted, scalar fragment loads) ----------------
// C = A (MxK) @ B^T (B is [N,K]).  Block tile 128x128, K-tile 16, 256 threads,
// warp tile 64x32 (2x4 warp grid).
template <bool BIAS, bool RES, bool GELU>
__global__ void __launch_bounds__(256)
gemm_kernel(const float* __restrict__ A, const float* __restrict__ B,
            const float* __restrict__ bias, const float* __restrict__ res,
            float* __restrict__ C, int M, int N, int K) {
    __shared__ float sA[2][128 * 20];
    __shared__ float sB[2][128 * 20];

    const int m0 = blockIdx.y * 128;
    const int n0 = blockIdx.x * 128;
    const int t = threadIdx.x;
    const int warp = t >> 5, lane = t & 31;
    const int wm = (warp & 1) * 64, wn = (warp >> 1) * 32;
    const int g = lane >> 2, tg = lane & 3;

    float acc[4][4][4];
#pragma unroll
    for (int i = 0; i < 4; i++)
#pragma unroll
        for (int j = 0; j < 4; j++)
#pragma unroll
            for (int r = 0; r < 4; r++) acc[i][j][r] = 0.f;

    const int nk = K >> 4;
    float4 ra[2], rb[2];
    const int arow = t >> 2, ac = (t & 3) * 4;

    auto gload = [&](int kt) {
        const int k0 = kt << 4;
#pragma unroll
        for (int u = 0; u < 2; u++)
            ra[u] = *(const float4*)(A + (long long)(m0 + arow + u * 64) * K + k0 + ac);
#pragma unroll
        for (int u = 0; u < 2; u++)
            rb[u] = *(const float4*)(B + (long long)(n0 + arow + u * 64) * K + k0 + ac);
    };

    auto sstore = [&](int buf) {
#pragma unroll
        for (int u = 0; u < 2; u++) {
            float* p = &sA[buf][(arow + u * 64) * 20 + ac];
            p[0] = f2tff(ra[u].x); p[1] = f2tff(ra[u].y);
            p[2] = f2tff(ra[u].z); p[3] = f2tff(ra[u].w);
        }
#pragma unroll
        for (int u = 0; u < 2; u++) {
            float* p = &sB[buf][(arow + u * 64) * 20 + ac];
            p[0] = f2tff(rb[u].x); p[1] = f2tff(rb[u].y);
            p[2] = f2tff(rb[u].z); p[3] = f2tff(rb[u].w);
        }
    };

    gload(0);
    sstore(0);
    __syncthreads();

    int buf = 0;
    for (int kt = 0; kt < nk; kt++) {
        if (kt + 1 < nk) gload(kt + 1);
#pragma unroll
        for (int ks = 0; ks < 16; ks += 8) {
            uint32_t af[4][4], bf[4][2];
#pragma unroll
            for (int i = 0; i < 4; i++) {
                const float* pa = &sA[buf][(wm + i * 16 + g) * 20 + ks + tg];
                af[i][0] = __float_as_uint(pa[0]);
                af[i][1] = __float_as_uint(pa[8 * 20]);
                af[i][2] = __float_as_uint(pa[4]);
                af[i][3] = __float_as_uint(pa[8 * 20 + 4]);
            }
#pragma unroll
            for (int j = 0; j < 4; j++) {
                const float* pb = &sB[buf][(wn + j * 8 + g) * 20 + ks + tg];
                bf[j][0] = __float_as_uint(pb[0]);
                bf[j][1] = __float_as_uint(pb[4]);
            }
#pragma unroll
            for (int i = 0; i < 4; i++)
#pragma unroll
                for (int j = 0; j < 4; j++) mma8(acc[i][j], af[i], bf[j]);
        }
        if (kt + 1 < nk) sstore(buf ^ 1);
        __syncthreads();
        buf ^= 1;
    }

#pragma unroll
    for (int i = 0; i < 4; i++) {
#pragma unroll
        for (int j = 0; j < 4; j++) {
            int m = m0 + wm + i * 16 + g;
            int n = n0 + wn + j * 8 + tg * 2;
#pragma unroll
            for (int r = 0; r < 4; r++) {
                int mm = m + (r >> 1) * 8;
                int nn = n + (r & 1);
                float v = acc[i][j][r];
                if (BIAS) v += bias[nn];
                if (GELU) v = v / (1.f + __expf(-1.702f * v));
                if (RES) v += res[(long long)mm * N + nn];
                C[(long long)mm * N + nn] = v;
            }
        }
    }
}

// ---------------- LayerNorm ----------------
__global__ void ln_kernel(const float* __restrict__ x, const float* __restrict__ gw,
                          const float* __restrict__ bw, float* __restrict__ out) {
    long long row = blockIdx.x;
    const float* xr = x + row * TD;
    float* orow = out + row * TD;
    int t = threadIdx.x;
    float v[3];
    float s = 0.f, s2 = 0.f;
#pragma unroll
    for (int i = 0; i < 3; i++) {
        v[i] = xr[t + i * 256];
        s += v[i];
        s2 += v[i] * v[i];
    }
#pragma unroll
    for (int o = 16; o > 0; o >>= 1) {
        s += __shfl_xor_sync(0xffffffffu, s, o);
        s2 += __shfl_xor_sync(0xffffffffu, s2, o);
    }
    __shared__ float r1[8], r2[8];
    if ((t & 31) == 0) { r1[t >> 5] = s; r2[t >> 5] = s2; }
    __syncthreads();
    s = 0.f; s2 = 0.f;
#pragma unroll
    for (int w = 0; w < 8; w++) { s += r1[w]; s2 += r2[w]; }
    float mu = s * (1.f / TD);
    float var = s2 * (1.f / TD) - mu * mu;
    float inv = rsqrtf(var + 1e-5f);
#pragma unroll
    for (int i = 0; i < 3; i++) {
        int c = t + i * 256;
        orow[c] = (v[i] - mu) * inv * gw[c] + bw[c];
    }
}

// ---------------- K/V gather, merged + vectorized ----------------
__global__ void gather_kv_kernel(const float* __restrict__ qkv, const float* __restrict__ prompt,
                                 float* __restrict__ Kd, float* __restrict__ Vd) {
    int i = blockIdx.x * 256 + threadIdx.x;          // float4 index
    const int TOT = TBH * TNK * (THD / 4);
    if (i >= TOT) return;
    int d4 = i & 15;
    int tmp = i >> 4;
    int j = tmp % TNK;
    int zz = tmp / TNK;
    int b = zz / TH, h = zz % TH;
    float4 kv, vv;
    if (j < TP) {
        kv = *(const float4*)(prompt + (((long long)(b * 2 + 0) * TP + j) * TH + h) * THD + d4 * 4);
        vv = *(const float4*)(prompt + (((long long)(b * 2 + 1) * TP + j) * TH + h) * THD + d4 * 4);
    } else {
        long long base = (long long)(b * TN + (j - TP)) * (3 * TD) + h * THD + d4 * 4;
        kv = *(const float4*)(qkv + base + TD);
        vv = *(const float4*)(qkv + base + 2 * TD);
    }
    ((float4*)Kd)[i] = kv;
    ((float4*)Vd)[i] = vv;
}

// ---------------- fused flash attention ----------------
// K stored row-major [key][d]; V stored TRANSPOSED [d][key] so the PV
// B-fragment loads are conflict-free (bank = 4g+tg, all distinct).
// All SMEM operands pre-converted to tf32 at staging.
#define FA_SMEM_BYTES ((2 * 64 * 68 + 128 * 68) * 4)

__global__ void __launch_bounds__(256)
flash_kernel(const float* __restrict__ qkv, const float* __restrict__ Kb,
             const float* __restrict__ Vb, float* __restrict__ O) {
    extern __shared__ float sm[];
    float* sK  = sm;                 // [64 keys][68]
    float* sVt = sm + 64 * 68;       // [64 d][68 keys]
    float* sP  = sm + 2 * 64 * 68;   // [128][68], also Q staging

    const int z = blockIdx.y;
    const int b = z / TH, h = z % TH;
    const int q0 = blockIdx.x * 128;
    const int t = threadIdx.x, warp = t >> 5, lane = t & 31;
    const int g = lane >> 2, tg = lane & 3;
    const int wm = warp * 16;

#pragma unroll
    for (int u = 0; u < 8; u++) {
        int idx = t + u * 256;
        int r = idx >> 4, c4 = (idx & 15) * 4;
        float4 v = *(const float4*)(qkv + (long long)(b * TN + q0 + r) * (3 * TD) + h * THD + c4);
        float* p = &sP[r * 68 + c4];
        p[0] = v.x; p[1] = v.y; p[2] = v.z; p[3] = v.w;
    }
    __syncthreads();
    uint32_t qf[8][4];
#pragma unroll
    for (int ks = 0; ks < 8; ks++) {
        const float* pa = &sP[(wm + g) * 68 + ks * 8 + tg];
        qf[ks][0] = f2tf(pa[0]);
        qf[ks][1] = f2tf(pa[8 * 68]);
        qf[ks][2] = f2tf(pa[4]);
        qf[ks][3] = f2tf(pa[8 * 68 + 4]);
    }
    __syncthreads();

    float acc[8][4];
#pragma unroll
    for (int j = 0; j < 8; j++)
#pragma unroll
        for (int r = 0; r < 4; r++) acc[j][r] = 0.f;
    float m0 = -1e30f, m1 = -1e30f, l0 = 0.f, l1 = 0.f;

    const float* Kz = Kb + (long long)z * TNK * THD;
    const float* Vz = Vb + (long long)z * TNK * THD;

    for (int t0 = 0; t0 < TNK; t0 += 64) {
        // K tile [64 keys][64 d], row-major, tf32 at store
#pragma unroll
        for (int u = 0; u < 4; u++) {
            int idx = t + u * 256;
            int r = idx >> 4, c4 = (idx & 15) * 4;
            int key = t0 + r;
            float4 kk;
            if (key < TNK) kk = *(const float4*)(Kz + (long long)key * THD + c4);
            else           kk = make_float4(0.f, 0.f, 0.f, 0.f);
            float* pk = &sK[r * 68 + c4];
            pk[0] = f2tff(kk.x); pk[1] = f2tff(kk.y);
            pk[2] = f2tff(kk.z); pk[3] = f2tff(kk.w);
        }
        // V tile transposed: sVt[d][key-r]. Coalesced global reads
        // (lanes sweep d), contiguous 4-wide SMEM stores per thread.
#pragma unroll
        for (int u = 0; u < 4; u++) {
            int idx = t + u * 256;
            int r4 = idx >> 6;          // 0..15 (key quad)
            int d = idx & 63;           // 0..63
            float vv[4];
#pragma unroll
            for (int e = 0; e < 4; e++) {
                int key = t0 + r4 * 4 + e;
                vv[e] = (key < TNK) ? Vz[(long long)key * THD + d] : 0.f;
            }
            float* pv = &sVt[d * 68 + r4 * 4];
            pv[0] = f2tff(vv[0]); pv[1] = f2tff(vv[1]);
            pv[2] = f2tff(vv[2]); pv[3] = f2tff(vv[3]);
        }
        __syncthreads();

        // S = Q @ K^T
        float s[8][4];
#pragma unroll
        for (int j = 0; j < 8; j++) {
            s[j][0] = s[j][1] = s[j][2] = s[j][3] = 0.f;
#pragma unroll
            for (int ks = 0; ks < 8; ks++) {
                uint32_t bf[2];
                const float* pb = &sK[(j * 8 + g) * 68 + ks * 8 + tg];
                bf[0] = __float_as_uint(pb[0]);
                bf[1] = __float_as_uint(pb[4]);
                mma8(s[j], qf[ks], bf);
            }
        }

        // online softmax
        float mx0 = -1e30f, mx1 = -1e30f;
#pragma unroll
        for (int j = 0; j < 8; j++) {
            int k0 = t0 + j * 8 + 2 * tg;
            if (k0 >= TNK) { s[j][0] = -1e30f; s[j][2] = -1e30f; }
            else           { s[j][0] *= 0.125f; s[j][2] *= 0.125f; }
            if (k0 + 1 >= TNK) { s[j][1] = -1e30f; s[j][3] = -1e30f; }
            else               { s[j][1] *= 0.125f; s[j][3] *= 0.125f; }
            mx0 = fmaxf(mx0, fmaxf(s[j][0], s[j][1]));
            mx1 = fmaxf(mx1, fmaxf(s[j][2], s[j][3]));
        }
        mx0 = fmaxf(mx0, __shfl_xor_sync(0xffffffffu, mx0, 1));
        mx0 = fmaxf(mx0, __shfl_xor_sync(0xffffffffu, mx0, 2));
        mx1 = fmaxf(mx1, __shfl_xor_sync(0xffffffffu, mx1, 1));
        mx1 = fmaxf(mx1, __shfl_xor_sync(0xffffffffu, mx1, 2));
        float mn0 = fmaxf(m0, mx0), mn1 = fmaxf(m1, mx1);
        float a0 = __expf(m0 - mn0), a1 = __expf(m1 - mn1);
        m0 = mn0; m1 = mn1;
        float sum0 = 0.f, sum1 = 0.f;
#pragma unroll
        for (int j = 0; j < 8; j++) {
            s[j][0] = __expf(s[j][0] - mn0);
            s[j][1] = __expf(s[j][1] - mn0);
            s[j][2] = __expf(s[j][2] - mn1);
            s[j][3] = __expf(s[j][3] - mn1);
            sum0 += s[j][0] + s[j][1];
            sum1 += s[j][2] + s[j][3];
            float* pp = &sP[(wm + g) * 68 + j * 8 + 2 * tg];
            pp[0] = f2tff(s[j][0]); pp[1] = f2tff(s[j][1]);
            pp[8 * 68] = f2tff(s[j][2]); pp[8 * 68 + 1] = f2tff(s[j][3]);
        }
        sum0 += __shfl_xor_sync(0xffffffffu, sum0, 1);
        sum0 += __shfl_xor_sync(0xffffffffu, sum0, 2);
        sum1 += __shfl_xor_sync(0xffffffffu, sum1, 1);
        sum1 += __shfl_xor_sync(0xffffffffu, sum1, 2);
        l0 = l0 * a0 + sum0;
        l1 = l1 * a1 + sum1;
#pragma unroll
        for (int j = 0; j < 8; j++) {
            acc[j][0] *= a0; acc[j][1] *= a0;
            acc[j][2] *= a1; acc[j][3] *= a1;
        }
        __syncwarp();

        // O += P @ V   (V read from transposed layout, conflict-free)
#pragma unroll
        for (int ks = 0; ks < 8; ks++) {
            uint32_t af[4];
            const float* pa = &sP[(wm + g) * 68 + ks * 8 + tg];
            af[0] = __float_as_uint(pa[0]);
            af[1] = __float_as_uint(pa[8 * 68]);
            af[2] = __float_as_uint(pa[4]);
            af[3] = __float_as_uint(pa[8 * 68 + 4]);
#pragma unroll
            for (int j = 0; j < 8; j++) {
                uint32_t bf[2];
                const float* pv = &sVt[(j * 8 + g) * 68 + ks * 8 + tg];
                bf[0] = __float_as_uint(pv[0]);
                bf[1] = __float_as_uint(pv[4]);
                mma8(acc[j], af, bf);
            }
        }
        __syncthreads();
    }

    float i0 = 1.f / l0, i1 = 1.f / l1;
    int q = q0 + wm + g;
#pragma unroll
    for (int j = 0; j < 8; j++) {
        long long base = ((long long)(b * TN + q)) * TD + h * THD + j * 8 + 2 * tg;
        O[base] = acc[j][0] * i0;
        O[base + 1] = acc[j][1] * i0;
        O[base + (long long)8 * TD] = acc[j][2] * i1;
        O[base + (long long)8 * TD + 1] = acc[j][3] * i1;
    }
}

// ---------------- launch ----------------
extern "C" void kernel_launch(void* const* d_in, const int* in_sizes, int n_in,
                              void* d_out, int out_size) {
    const float* x      = (const float*)d_in[0];
    const float* prompt = (const float*)d_in[1];
    const float* qkv_w  = (const float*)d_in[2];
    const float* qkv_b  = (const float*)d_in[3];
    const float* out_w  = (const float*)d_in[4];
    const float* out_b  = (const float*)d_in[5];
    const float* ln1_g  = (const float*)d_in[6];
    const float* ln1_b  = (const float*)d_in[7];
    const float* ln2_g  = (const float*)d_in[8];
    const float* ln2_b  = (const float*)d_in[9];
    const float* fc1_w  = (const float*)d_in[10];
    const float* fc1_b  = (const float*)d_in[11];
    const float* fc2_w  = (const float*)d_in[12];
    const float* fc2_b  = (const float*)d_in[13];
    float* out = (float*)d_out;

    float *ph, *pqkv, *pkb, *pvb, *pao, *px1, *pm;
    cudaGetSymbolAddress((void**)&ph, g_h);
    cudaGetSymbolAddress((void**)&pqkv, g_qkv);
    cudaGetSymbolAddress((void**)&pkb, g_kb);
    cudaGetSymbolAddress((void**)&pvb, g_vb);
    cudaGetSymbolAddress((void**)&pao, g_ao);
    cudaGetSymbolAddress((void**)&px1, g_x1);
    cudaGetSymbolAddress((void**)&pm, g_mm);

    cudaFuncSetAttribute(flash_kernel, cudaFuncAttributeMaxDynamicSharedMemorySize,
                         FA_SMEM_BYTES);

    // 1. LN1
    ln_kernel<<<TM, 256>>>(x, ln1_g, ln1_b, ph);

    // 2. qkv = h @ qkv_w^T + qkv_b
    gemm_kernel<true, false, false>
        <<<dim3(3 * TD / 128, TM / 128), 256>>>(ph, qkv_w, qkv_b, nullptr, pqkv,
                                                TM, 3 * TD, TD);

    // 3. gather K/V (prompt concat), merged
    gather_kv_kernel<<<(TBH * TNK * (THD / 4) + 255) / 256, 256>>>(pqkv, prompt, pkb, pvb);

    // 4. fused flash attention -> [B,N,D]
    flash_kernel<<<dim3(TN / 128, TBH), 256, FA_SMEM_BYTES>>>(pqkv, pkb, pvb, pao);

    // 5. x1 = x + O @ out_w^T + out_b
    gemm_kernel<true, true, false>
        <<<dim3(TD / 128, TM / 128), 256>>>(pao, out_w, out_b, x, px1, TM, TD, TD);

    // 6. LN2
    ln_kernel<<<TM, 256>>>(px1, ln2_g, ln2_b, ph);

    // 7. m = QuickGELU(h @ fc1_w^T + fc1_b)
    gemm_kernel<true, false, true>
        <<<dim3(TFF / 128, TM / 128), 256>>>(ph, fc1_w, fc1_b, nullptr, pm, TM, TFF, TD);

    // 8. out = x1 + m @ fc2_w^T + fc2_b
    gemm_kernel<true, true, false>
        <<<dim3(TD / 128, TM / 128), 256>>>(pm, fc2_w, fc2_b, px1, out, TM, TD, TFF);
}

// round 12
// speedup vs baseline: 1.6604x; 1.3477x over previous
#include <cuda_runtime.h>
#include <cuda_fp16.h>
#include <cstdint>

// ---------------- problem constants ----------------
#define TB 16
#define TN 1024
#define TD 768
#define TH 12
#define TP 16
#define THD 64
#define TFF 3072
#define TNK (TP + TN)      // 1040
#define TBH (TB * TH)      // 192
#define TM (TB * TN)       // 16384

// ---------------- scratch ----------------
__device__ float g_h[(size_t)TM * TD];
__device__ float g_qkv[(size_t)TM * 3 * TD];
__device__ float g_kb[(size_t)TBH * TNK * THD];
__device__ float g_vb[(size_t)TBH * TNK * THD];
__device__ float g_ao[(size_t)TM * TD];
__device__ float g_x1[(size_t)TM * TD];
__device__ float g_mm[(size_t)TM * TFF];

// ---------------- helpers ----------------
__device__ __forceinline__ uint32_t f2tf(float f) {
    uint32_t u;
    asm("cvt.rna.tf32.f32 %0, %1;" : "=r"(u) : "f"(f));
    return u;
}
__device__ __forceinline__ float f2tff(float f) {
    return __uint_as_float(f2tf(f));
}
__device__ __forceinline__ uint32_t f2h2(float x, float y) {
    __half2 h = __floats2half2_rn(x, y);   // x in low half
    return *reinterpret_cast<uint32_t*>(&h);
}

// tf32 m16n8k8 (used by flash)
__device__ __forceinline__ void mma8(float c[4], const uint32_t a[4], const uint32_t b[2]) {
    asm volatile(
        "mma.sync.aligned.m16n8k8.row.col.f32.tf32.tf32.f32 "
        "{%0,%1,%2,%3},{%4,%5,%6,%7},{%8,%9},{%0,%1,%2,%3};\n"
        : "+f"(c[0]), "+f"(c[1]), "+f"(c[2]), "+f"(c[3])
        : "r"(a[0]), "r"(a[1]), "r"(a[2]), "r"(a[3]), "r"(b[0]), "r"(b[1]));
}

// fp16 m16n8k16 (dense GEMMs)
__device__ __forceinline__ void mma16(float c[4], const uint32_t a[4], const uint32_t b[2]) {
    asm volatile(
        "mma.sync.aligned.m16n8k16.row.col.f32.f16.f16.f32 "
        "{%0,%1,%2,%3},{%4,%5,%6,%7},{%8,%9},{%0,%1,%2,%3};\n"
        : "+f"(c[0]), "+f"(c[1]), "+f"(c[2]), "+f"(c[3])
        : "r"(a[0]), "r"(a[1]), "r"(a[2]), "r"(a[3]), "r"(b[0]), "r"(b[1]));
}

// ---------------- tiled FP16 GEMM ----------------
// C = A (MxK) @ B^T (B is [N,K]).  Block tile 128x128, K-tile 16, 256 threads,
// warp tile 64x32 (2x4 warp grid), m16n8k16 fp16 MMA, fp32 accumulate.
// SMEM: halves packed in uint32 (2 per reg), row stride 12 uint32 (8 data + 4 pad).
// Fragment-load banks: (12*row + tg) mod 32 -> 32 distinct, conflict-free.
template <bool BIAS, bool RES, bool GELU>
__global__ void __launch_bounds__(256)
gemm_kernel(const float* __restrict__ A, const float* __restrict__ B,
            const float* __restrict__ bias, const float* __restrict__ res,
            float* __restrict__ C, int M, int N, int K) {
    __shared__ uint32_t sA[2][128 * 12];
    __shared__ uint32_t sB[2][128 * 12];

    const int m0 = blockIdx.y * 128;
    const int n0 = blockIdx.x * 128;
    const int t = threadIdx.x;
    const int warp = t >> 5, lane = t & 31;
    const int wm = (warp & 1) * 64, wn = (warp >> 1) * 32;
    const int g = lane >> 2, tg = lane & 3;

    float acc[4][4][4];
#pragma unroll
    for (int i = 0; i < 4; i++)
#pragma unroll
        for (int j = 0; j < 4; j++)
#pragma unroll
            for (int r = 0; r < 4; r++) acc[i][j][r] = 0.f;

    const int nk = K >> 4;
    float4 ra[2], rb[2];
    const int arow = t >> 2, ac = (t & 3) * 4;   // ac = k offset (halves)

    auto gload = [&](int kt) {
        const int k0 = kt << 4;
#pragma unroll
        for (int u = 0; u < 2; u++)
            ra[u] = *(const float4*)(A + (long long)(m0 + arow + u * 64) * K + k0 + ac);
#pragma unroll
        for (int u = 0; u < 2; u++)
            rb[u] = *(const float4*)(B + (long long)(n0 + arow + u * 64) * K + k0 + ac);
    };

    auto sstore = [&](int buf) {
#pragma unroll
        for (int u = 0; u < 2; u++) {
            int base = (arow + u * 64) * 12 + (ac >> 1);
            sA[buf][base]     = f2h2(ra[u].x, ra[u].y);
            sA[buf][base + 1] = f2h2(ra[u].z, ra[u].w);
        }
#pragma unroll
        for (int u = 0; u < 2; u++) {
            int base = (arow + u * 64) * 12 + (ac >> 1);
            sB[buf][base]     = f2h2(rb[u].x, rb[u].y);
            sB[buf][base + 1] = f2h2(rb[u].z, rb[u].w);
        }
    };

    gload(0);
    sstore(0);
    __syncthreads();

    int buf = 0;
    for (int kt = 0; kt < nk; kt++) {
        if (kt + 1 < nk) gload(kt + 1);
        uint32_t af[4][4], bf[4][2];
#pragma unroll
        for (int i = 0; i < 4; i++) {
            int r = (wm + i * 16 + g) * 12;
            af[i][0] = sA[buf][r + tg];              // (row g,   k 2tg..2tg+1)
            af[i][1] = sA[buf][r + 96 + tg];         // (row g+8, k 2tg..2tg+1)
            af[i][2] = sA[buf][r + tg + 4];          // (row g,   k 2tg+8..+9)
            af[i][3] = sA[buf][r + 96 + tg + 4];     // (row g+8, k 2tg+8..+9)
        }
#pragma unroll
        for (int j = 0; j < 4; j++) {
            int rn = (wn + j * 8 + g) * 12;
            bf[j][0] = sB[buf][rn + tg];             // (k 2tg..2tg+1,  col g)
            bf[j][1] = sB[buf][rn + tg + 4];         // (k 2tg+8..+9,   col g)
        }
#pragma unroll
        for (int i = 0; i < 4; i++)
#pragma unroll
            for (int j = 0; j < 4; j++) mma16(acc[i][j], af[i], bf[j]);
        if (kt + 1 < nk) sstore(buf ^ 1);
        __syncthreads();
        buf ^= 1;
    }

#pragma unroll
    for (int i = 0; i < 4; i++) {
#pragma unroll
        for (int j = 0; j < 4; j++) {
            int m = m0 + wm + i * 16 + g;
            int n = n0 + wn + j * 8 + tg * 2;
#pragma unroll
            for (int r = 0; r < 4; r++) {
                int mm = m + (r >> 1) * 8;
                int nn = n + (r & 1);
                float v = acc[i][j][r];
                if (BIAS) v += bias[nn];
                if (GELU) v = v / (1.f + __expf(-1.702f * v));
                if (RES) v += res[(long long)mm * N + nn];
                C[(long long)mm * N + nn] = v;
            }
        }
    }
}

// ---------------- LayerNorm ----------------
__global__ void ln_kernel(const float* __restrict__ x, const float* __restrict__ gw,
                          const float* __restrict__ bw, float* __restrict__ out) {
    long long row = blockIdx.x;
    const float* xr = x + row * TD;
    float* orow = out + row * TD;
    int t = threadIdx.x;
    float v[3];
    float s = 0.f, s2 = 0.f;
#pragma unroll
    for (int i = 0; i < 3; i++) {
        v[i] = xr[t + i * 256];
        s += v[i];
        s2 += v[i] * v[i];
    }
#pragma unroll
    for (int o = 16; o > 0; o >>= 1) {
        s += __shfl_xor_sync(0xffffffffu, s, o);
        s2 += __shfl_xor_sync(0xffffffffu, s2, o);
    }
    __shared__ float r1[8], r2[8];
    if ((t & 31) == 0) { r1[t >> 5] = s; r2[t >> 5] = s2; }
    __syncthreads();
    s = 0.f; s2 = 0.f;
#pragma unroll
    for (int w = 0; w < 8; w++) { s += r1[w]; s2 += r2[w]; }
    float mu = s * (1.f / TD);
    float var = s2 * (1.f / TD) - mu * mu;
    float inv = rsqrtf(var + 1e-5f);
#pragma unroll
    for (int i = 0; i < 3; i++) {
        int c = t + i * 256;
        orow[c] = (v[i] - mu) * inv * gw[c] + bw[c];
    }
}

// ---------------- K/V gather, merged + vectorized ----------------
__global__ void gather_kv_kernel(const float* __restrict__ qkv, const float* __restrict__ prompt,
                                 float* __restrict__ Kd, float* __restrict__ Vd) {
    int i = blockIdx.x * 256 + threadIdx.x;          // float4 index
    const int TOT = TBH * TNK * (THD / 4);
    if (i >= TOT) return;
    int d4 = i & 15;
    int tmp = i >> 4;
    int j = tmp % TNK;
    int zz = tmp / TNK;
    int b = zz / TH, h = zz % TH;
    float4 kv, vv;
    if (j < TP) {
        kv = *(const float4*)(prompt + (((long long)(b * 2 + 0) * TP + j) * TH + h) * THD + d4 * 4);
        vv = *(const float4*)(prompt + (((long long)(b * 2 + 1) * TP + j) * TH + h) * THD + d4 * 4);
    } else {
        long long base = (long long)(b * TN + (j - TP)) * (3 * TD) + h * THD + d4 * 4;
        kv = *(const float4*)(qkv + base + TD);
        vv = *(const float4*)(qkv + base + 2 * TD);
    }
    ((float4*)Kd)[i] = kv;
    ((float4*)Vd)[i] = vv;
}

// ---------------- fused flash attention (R11 winning version, unchanged) ----
#define FA_SMEM_BYTES ((2 * 64 * 68 + 128 * 68) * 4)

__global__ void __launch_bounds__(256)
flash_kernel(const float* __restrict__ qkv, const float* __restrict__ Kb,
             const float* __restrict__ Vb, float* __restrict__ O) {
    extern __shared__ float sm[];
    float* sK  = sm;                 // [64 keys][68]
    float* sVt = sm + 64 * 68;       // [64 d][68 keys]
    float* sP  = sm + 2 * 64 * 68;   // [128][68], also Q staging

    const int z = blockIdx.y;
    const int b = z / TH, h = z % TH;
    const int q0 = blockIdx.x * 128;
    const int t = threadIdx.x, warp = t >> 5, lane = t & 31;
    const int g = lane >> 2, tg = lane & 3;
    const int wm = warp * 16;

#pragma unroll
    for (int u = 0; u < 8; u++) {
        int idx = t + u * 256;
        int r = idx >> 4, c4 = (idx & 15) * 4;
        float4 v = *(const float4*)(qkv + (long long)(b * TN + q0 + r) * (3 * TD) + h * THD + c4);
        float* p = &sP[r * 68 + c4];
        p[0] = v.x; p[1] = v.y; p[2] = v.z; p[3] = v.w;
    }
    __syncthreads();
    uint32_t qf[8][4];
#pragma unroll
    for (int ks = 0; ks < 8; ks++) {
        const float* pa = &sP[(wm + g) * 68 + ks * 8 + tg];
        qf[ks][0] = f2tf(pa[0]);
        qf[ks][1] = f2tf(pa[8 * 68]);
        qf[ks][2] = f2tf(pa[4]);
        qf[ks][3] = f2tf(pa[8 * 68 + 4]);
    }
    __syncthreads();

    float acc[8][4];
#pragma unroll
    for (int j = 0; j < 8; j++)
#pragma unroll
        for (int r = 0; r < 4; r++) acc[j][r] = 0.f;
    float m0 = -1e30f, m1 = -1e30f, l0 = 0.f, l1 = 0.f;

    const float* Kz = Kb + (long long)z * TNK * THD;
    const float* Vz = Vb + (long long)z * TNK * THD;

    for (int t0 = 0; t0 < TNK; t0 += 64) {
#pragma unroll
        for (int u = 0; u < 4; u++) {
            int idx = t + u * 256;
            int r = idx >> 4, c4 = (idx & 15) * 4;
            int key = t0 + r;
            float4 kk;
            if (key < TNK) kk = *(const float4*)(Kz + (long long)key * THD + c4);
            else           kk = make_float4(0.f, 0.f, 0.f, 0.f);
            float* pk = &sK[r * 68 + c4];
            pk[0] = f2tff(kk.x); pk[1] = f2tff(kk.y);
            pk[2] = f2tff(kk.z); pk[3] = f2tff(kk.w);
        }
#pragma unroll
        for (int u = 0; u < 4; u++) {
            int idx = t + u * 256;
            int r4 = idx >> 6;          // 0..15 (key quad)
            int d = idx & 63;           // 0..63
            float vv[4];
#pragma unroll
            for (int e = 0; e < 4; e++) {
                int key = t0 + r4 * 4 + e;
                vv[e] = (key < TNK) ? Vz[(long long)key * THD + d] : 0.f;
            }
            float* pv = &sVt[d * 68 + r4 * 4];
            pv[0] = f2tff(vv[0]); pv[1] = f2tff(vv[1]);
            pv[2] = f2tff(vv[2]); pv[3] = f2tff(vv[3]);
        }
        __syncthreads();

        float s[8][4];
#pragma unroll
        for (int j = 0; j < 8; j++) {
            s[j][0] = s[j][1] = s[j][2] = s[j][3] = 0.f;
#pragma unroll
            for (int ks = 0; ks < 8; ks++) {
                uint32_t bf[2];
                const float* pb = &sK[(j * 8 + g) * 68 + ks * 8 + tg];
                bf[0] = __float_as_uint(pb[0]);
                bf[1] = __float_as_uint(pb[4]);
                mma8(s[j], qf[ks], bf);
            }
        }

        float mx0 = -1e30f, mx1 = -1e30f;
#pragma unroll
        for (int j = 0; j < 8; j++) {
            int k0 = t0 + j * 8 + 2 * tg;
            if (k0 >= TNK) { s[j][0] = -1e30f; s[j][2] = -1e30f; }
            else           { s[j][0] *= 0.125f; s[j][2] *= 0.125f; }
            if (k0 + 1 >= TNK) { s[j][1] = -1e30f; s[j][3] = -1e30f; }
            else               { s[j][1] *= 0.125f; s[j][3] *= 0.125f; }
            mx0 = fmaxf(mx0, fmaxf(s[j][0], s[j][1]));
            mx1 = fmaxf(mx1, fmaxf(s[j][2], s[j][3]));
        }
        mx0 = fmaxf(mx0, __shfl_xor_sync(0xffffffffu, mx0, 1));
        mx0 = fmaxf(mx0, __shfl_xor_sync(0xffffffffu, mx0, 2));
        mx1 = fmaxf(mx1, __shfl_xor_sync(0xffffffffu, mx1, 1));
        mx1 = fmaxf(mx1, __shfl_xor_sync(0xffffffffu, mx1, 2));
        float mn0 = fmaxf(m0, mx0), mn1 = fmaxf(m1, mx1);
        float a0 = __expf(m0 - mn0), a1 = __expf(m1 - mn1);
        m0 = mn0; m1 = mn1;
        float sum0 = 0.f, sum1 = 0.f;
#pragma unroll
        for (int j = 0; j < 8; j++) {
            s[j][0] = __expf(s[j][0] - mn0);
            s[j][1] = __expf(s[j][1] - mn0);
            s[j][2] = __expf(s[j][2] - mn1);
            s[j][3] = __expf(s[j][3] - mn1);
            sum0 += s[j][0] + s[j][1];
            sum1 += s[j][2] + s[j][3];
            float* pp = &sP[(wm + g) * 68 + j * 8 + 2 * tg];
            pp[0] = f2tff(s[j][0]); pp[1] = f2tff(s[j][1]);
            pp[8 * 68] = f2tff(s[j][2]); pp[8 * 68 + 1] = f2tff(s[j][3]);
        }
        sum0 += __shfl_xor_sync(0xffffffffu, sum0, 1);
        sum0 += __shfl_xor_sync(0xffffffffu, sum0, 2);
        sum1 += __shfl_xor_sync(0xffffffffu, sum1, 1);
        sum1 += __shfl_xor_sync(0xffffffffu, sum1, 2);
        l0 = l0 * a0 + sum0;
        l1 = l1 * a1 + sum1;
#pragma unroll
        for (int j = 0; j < 8; j++) {
            acc[j][0] *= a0; acc[j][1] *= a0;
            acc[j][2] *= a1; acc[j][3] *= a1;
        }
        __syncwarp();

#pragma unroll
        for (int ks = 0; ks < 8; ks++) {
            uint32_t af[4];
            const float* pa = &sP[(wm + g) * 68 + ks * 8 + tg];
            af[0] = __float_as_uint(pa[0]);
            af[1] = __float_as_uint(pa[8 * 68]);
            af[2] = __float_as_uint(pa[4]);
            af[3] = __float_as_uint(pa[8 * 68 + 4]);
#pragma unroll
            for (int j = 0; j < 8; j++) {
                uint32_t bf[2];
                const float* pv = &sVt[(j * 8 + g) * 68 + ks * 8 + tg];
                bf[0] = __float_as_uint(pv[0]);
                bf[1] = __float_as_uint(pv[4]);
                mma8(acc[j], af, bf);
            }
        }
        __syncthreads();
    }

    float i0 = 1.f / l0, i1 = 1.f / l1;
    int q = q0 + wm + g;
#pragma unroll
    for (int j = 0; j < 8; j++) {
        long long base = ((long long)(b * TN + q)) * TD + h * THD + j * 8 + 2 * tg;
        O[base] = acc[j][0] * i0;
        O[base + 1] = acc[j][1] * i0;
        O[base + (long long)8 * TD] = acc[j][2] * i1;
        O[base + (long long)8 * TD + 1] = acc[j][3] * i1;
    }
}

// ---------------- launch ----------------
extern "C" void kernel_launch(void* const* d_in, const int* in_sizes, int n_in,
                              void* d_out, int out_size) {
    const float* x      = (const float*)d_in[0];
    const float* prompt = (const float*)d_in[1];
    const float* qkv_w  = (const float*)d_in[2];
    const float* qkv_b  = (const float*)d_in[3];
    const float* out_w  = (const float*)d_in[4];
    const float* out_b  = (const float*)d_in[5];
    const float* ln1_g  = (const float*)d_in[6];
    const float* ln1_b  = (const float*)d_in[7];
    const float* ln2_g  = (const float*)d_in[8];
    const float* ln2_b  = (const float*)d_in[9];
    const float* fc1_w  = (const float*)d_in[10];
    const float* fc1_b  = (const float*)d_in[11];
    const float* fc2_w  = (const float*)d_in[12];
    const float* fc2_b  = (const float*)d_in[13];
    float* out = (float*)d_out;

    float *ph, *pqkv, *pkb, *pvb, *pao, *px1, *pm;
    cudaGetSymbolAddress((void**)&ph, g_h);
    cudaGetSymbolAddress((void**)&pqkv, g_qkv);
    cudaGetSymbolAddress((void**)&pkb, g_kb);
    cudaGetSymbolAddress((void**)&pvb, g_vb);
    cudaGetSymbolAddress((void**)&pao, g_ao);
    cudaGetSymbolAddress((void**)&px1, g_x1);
    cudaGetSymbolAddress((void**)&pm, g_mm);

    cudaFuncSetAttribute(flash_kernel, cudaFuncAttributeMaxDynamicSharedMemorySize,
                         FA_SMEM_BYTES);

    // 1. LN1
    ln_kernel<<<TM, 256>>>(x, ln1_g, ln1_b, ph);

    // 2. qkv = h @ qkv_w^T + qkv_b
    gemm_kernel<true, false, false>
        <<<dim3(3 * TD / 128, TM / 128), 256>>>(ph, qkv_w, qkv_b, nullptr, pqkv,
                                                TM, 3 * TD, TD);

    // 3. gather K/V (prompt concat), merged
    gather_kv_kernel<<<(TBH * TNK * (THD / 4) + 255) / 256, 256>>>(pqkv, prompt, pkb, pvb);

    // 4. fused flash attention -> [B,N,D]
    flash_kernel<<<dim3(TN / 128, TBH), 256, FA_SMEM_BYTES>>>(pqkv, pkb, pvb, pao);

    // 5. x1 = x + O @ out_w^T + out_b
    gemm_kernel<true, true, false>
        <<<dim3(TD / 128, TM / 128), 256>>>(pao, out_w, out_b, x, px1, TM, TD, TD);

    // 6. LN2
    ln_kernel<<<TM, 256>>>(px1, ln2_g, ln2_b, ph);

    // 7. m = QuickGELU(h @ fc1_w^T + fc1_b)
    gemm_kernel<true, false, true>
        <<<dim3(TFF / 128, TM / 128), 256>>>(ph, fc1_w, fc1_b, nullptr, pm, TM, TFF, TD);

    // 8. out = x1 + m @ fc2_w^T + fc2_b
    gemm_kernel<true, true, false>
        <<<dim3(TD / 128, TM / 128), 256>>>(pm, fc2_w, fc2_b, px1, out, TM, TD, TFF);
}